// round 12
// baseline (speedup 1.0000x reference)
#include <cuda_runtime.h>
#include <math_constants.h>

// Problem constants (from reference setup_inputs)
static constexpr int NB  = 16;   // batch
static constexpr int CIN = 32;   // input channels
static constexpr int DIN = 16;
static constexpr int HIN = 32;
static constexpr int WIN = 32;
static constexpr int ODp = 5;    // pooled output dims
static constexpr int OHp = 10;
static constexpr int OWp = 10;
static constexpr int NOUT = NB * ODp * OHp * OWp;   // 8000

// 4 chunks of 8 channels staged; each warp computes 4 (its channel half).
static constexpr int CHUNK = 8;
static constexpr int CPG   = 4;                        // channels per group
static constexpr int LWP   = 33;                       // padded x row (conflict-free)
static constexpr int XS_ELEMS  = CHUNK * 4 * 5 * LWP;  // 5280 (<=4 d-slabs/half)
static constexpr int PM2_ELEMS = 2 * 2 * 30 * 18;      // [pb][group][cell][pt]
static constexpr int PMM_ELEMS = 60;
static constexpr int SMEM_BYTES = (XS_ELEMS + PM2_ELEMS + PMM_ELEMS) * 4; // 30,000 B

// wsum padded: [c][kd*5+kh][8] (5 kw + 3 ZERO pads -> {W4,0} 64-bit loads);
// [6400] = bias_sum
__device__ float g_wsum_pad[6404];
// Per-half pooled maxima (pre-bias), combined by pass 2.
__device__ float g_half[2][NOUT];

typedef unsigned long long ull;

#define FMA2(d, a, b) \
    asm("fma.rn.f32x2 %0, %1, %2, %0;" : "+l"(d) : "l"(a), "l"(b))

__device__ __forceinline__ ull bcast2(float x) {
    ull r;
    asm("mov.b64 %0, {%1, %1};" : "=l"(r) : "f"(x));
    return r;
}
__device__ __forceinline__ float2 unpack2(ull v) {
    float lo, hi;
    asm("mov.b64 {%0, %1}, %2;" : "=f"(lo), "=f"(hi) : "l"(v));
    return make_float2(lo, hi);
}

// ---------------------------------------------------------------------------
// Kernel 1: wsum[c][row][kw] = sum_o weight[c][o][kd,kh,kw] (pads = 0);
// bias_sum at [6400].  weight layout: (32,64,5,5,5) -> c*8000 + o*125 + k
// ---------------------------------------------------------------------------
__global__ void prep_kernel(const float* __restrict__ weight,
                            const float* __restrict__ bias) {
    int idx = blockIdx.x * blockDim.x + threadIdx.x;
    if (idx < 6400) {
        int c   = idx / 200;
        int rem = idx - c * 200;
        int row = rem >> 3;
        int col = rem & 7;
        float s = 0.f;
        if (col < 5) {
            const float* p = weight + c * 8000 + row * 5 + col;
            #pragma unroll 8
            for (int o = 0; o < 64; o++) s += p[o * 125];
        }
        g_wsum_pad[idx] = s;   // pads (col>=5) get 0
    } else if (idx == 6400) {
        float s = 0.f;
        #pragma unroll
        for (int o = 0; o < 64; o++) s += bias[o];
        g_wsum_pad[6400] = s;
    }
}

// ---------------------------------------------------------------------------
// Per-chunk compute for oh-parity PB, od-half H, channels [C0, C0+CPG).
// Thread owns 3 local od (global od = od_loc + 3H) x 6 ow = 18 y partials
// as 9 f32x2 accumulators acc[od_loc*3 + owpair].
// Local slab ld_s maps to global ld = ld_s + 2H (half0 stages slabs 0..3,
// half1 stages slabs 2..4).  od_loc = 2*ld_s + kd - 4 + H, valid in [0,2].
// ---------------------------------------------------------------------------
template <int PB, int H>
__device__ __forceinline__ void compute_chunk(const float* __restrict__ XS,
                                              const float* __restrict__ gw,
                                              int C0, int b_off, int w,
                                              ull (&acc)[9]) {
    constexpr int NT    = 3 - PB;    // # kh taps
    constexpr int LDMAX = 4 - H;     // # local d-slabs
    const int xcol = 3 * w;

    for (int c = C0; c < C0 + CPG; c++) {
        const float* XC = XS + c * (20 * LWP);
        const float* WC = gw + c * 200;
        #pragma unroll
        for (int t = 0; t < NT; t++) {
            const int lh = b_off + 2 - t;
            const int kh = PB + 2 * t;
            // Hoist all 5 kd weight rows for this kh (uniform 64-bit LDG).
            ull W01[5], W23[5], W40[5];
            #pragma unroll
            for (int kd = 0; kd < 5; kd++) {
                const ull* wr = reinterpret_cast<const ull*>(
                    WC + (kd * 5 + kh) * 8);
                W01[kd] = __ldg(wr);
                W23[kd] = __ldg(wr + 1);
                W40[kd] = __ldg(wr + 2);   // {W4, 0} thanks to zero padding
            }
            #pragma unroll
            for (int ld = 0; ld < LDMAX; ld++) {
                const float* Xr = XC + (ld * 5 + lh) * LWP + xcol;
                const ull XX0 = bcast2(Xr[0]);
                const ull XX1 = bcast2(Xr[1]);
                const ull XX2 = bcast2(Xr[2]);
                const ull XX3 = bcast2(Xr[3]);
                const ull XX4 = bcast2(Xr[4]);
                #pragma unroll
                for (int kd = 0; kd < 5; kd++) {
                    const int od = 2 * ld + kd - 4 + H;   // local od
                    if (od < 0 || od > 2) continue;       // folds at compile time
                    ull* P = acc + od * 3;
                    FMA2(P[0], XX2, W01[kd]);
                    FMA2(P[0], XX1, W23[kd]);
                    FMA2(P[0], XX0, W40[kd]);
                    FMA2(P[1], XX3, W01[kd]);
                    FMA2(P[1], XX2, W23[kd]);
                    FMA2(P[1], XX1, W40[kd]);
                    FMA2(P[2], XX4, W01[kd]);
                    FMA2(P[2], XX3, W23[kd]);
                    FMA2(P[2], XX2, W40[kd]);
                }
            }
        }
    }
}

// ---------------------------------------------------------------------------
// Kernel 2: fused transposed-conv (channel-summed) + half the 6x6x6 pool.
// Block = (n, d, h, H=od-half); 128 threads = 4 warps = (pb, channel-half);
// pb mapping swapped by block parity to average SMSP load.
// Lanes 0..29 own (b_off, w); each thread computes 18 y-partials.
// ---------------------------------------------------------------------------
__global__ __launch_bounds__(128, 6)
void fused_kernel(const float* __restrict__ x) {
    extern __shared__ float smem[];
    float* XS  = smem;                          // [8][<=4][5][LWP]
    float* PM2 = smem + XS_ELEMS;               // [2 pb][2 group][30][18]
    float* PMM = PM2 + PM2_ELEMS;               // [2 pb][30]

    const int h = blockIdx.x;
    const int d = blockIdx.y;
    const int n = blockIdx.z >> 1;
    const int H = blockIdx.z & 1;               // od half: 0 -> od 0..2, 1 -> 3..5
    const int tid   = threadIdx.x;
    const int wid   = tid >> 5;
    const int lane  = tid & 31;
    const int par   = (blockIdx.x + blockIdx.y + blockIdx.z) & 1;
    const int pb    = (wid >> 1) ^ par;    // oh parity (block-parity swapped)
    const int group = wid & 1;             // channel half
    const int C0    = group * CPG;
    const int b_off = lane / 10;           // 0..2 (lanes 30,31: garbage, unstored)
    const int w     = lane - b_off * 10;

    const int id0 = 3 * d - 1 + 2 * H;     // global id of local slab 0
    const int ih0 = 3 * h - 1;
    const int NROWS = 20 - 5 * H;          // local rows staged (4 or 3 slabs)
    const float* xn = x + (long)n * (CIN * DIN * HIN * WIN);

    // --- precompute staging row tables: rows r = wid + 4*rr, rr < 5 ---
    bool rok[5], vld[5];
    int  goff[5], doff[5];
    #pragma unroll
    for (int rr = 0; rr < 5; rr++) {
        int r  = wid + 4 * rr;
        rok[rr] = (r < NROWS);
        int rc = r < NROWS ? r : 0;
        int ld = rc / 5;                    // local slab
        int lh = rc - ld * 5;
        int id = id0 + ld;                  // global id (<= 15 always)
        int ih = ih0 + lh;
        vld[rr]  = (id >= 0) && (ih >= 0);  // upper bounds always in range
        goff[rr] = id * (HIN * WIN) + ih * WIN + lane;
        doff[rr] = rc * LWP + 1 + lane;     // lw = iw + 1
    }

    ull acc[9];
    #pragma unroll
    for (int i = 0; i < 9; i++) acc[i] = 0ull;

    for (int chunk = 0; chunk < 4; chunk++) {
        if (chunk) __syncthreads();          // protect XS before re-staging
        // ---- stage x chunk (8 channels): lanes map 1:1 to iw, coalesced ----
        const float* xc = xn + chunk * (CHUNK * DIN * HIN * WIN);
        for (int c = 0; c < CHUNK; c++) {
            const int bg = c * (DIN * HIN * WIN);
            const int bd = c * (20 * LWP);
            #pragma unroll
            for (int rr = 0; rr < 5; rr++) {
                if (rok[rr]) {
                    float v = vld[rr] ? __ldg(xc + bg + goff[rr]) : 0.f;
                    XS[bd + doff[rr]] = v;
                    if (lane == 0) XS[bd + doff[rr] - 1] = 0.f;  // lw=0 pad col
                }
            }
        }
        __syncthreads();

        const float* gw = g_wsum_pad + chunk * (CHUNK * 200);
        if (H == 0) {
            if (pb == 0) compute_chunk<0, 0>(XS, gw, C0, b_off, w, acc);
            else         compute_chunk<1, 0>(XS, gw, C0, b_off, w, acc);
        } else {
            if (pb == 0) compute_chunk<0, 1>(XS, gw, C0, b_off, w, acc);
            else         compute_chunk<1, 1>(XS, gw, C0, b_off, w, acc);
        }
    }
    __syncthreads();

    // ---- store this (pb, group) 18 channel-partials for the cell ----
    if (lane < 30) {
        float* P = PM2 + ((pb * 2 + group) * 30 + lane) * 18;
        #pragma unroll
        for (int i = 0; i < 9; i++) {
            float2 v = unpack2(acc[i]);
            P[2 * i]     = v.x;
            P[2 * i + 1] = v.y;
        }
    }
    __syncthreads();

    // ---- per (pb, cell): sum the two channel-groups, max over 18 pts ----
    if (tid < 60) {
        const int p2   = tid / 30;
        const int cell = tid - p2 * 30;
        const float* A = PM2 + (p2 * 2 * 30 + cell) * 18;   // group 0
        const float* B = A + 30 * 18;                        // group 1
        float m = -CUDART_INF_F;
        #pragma unroll
        for (int i = 0; i < 18; i++) m = fmaxf(m, A[i] + B[i]);
        PMM[p2 * 30 + cell] = m;
    }
    __syncthreads();

    // ---- final: max over pb and b_off, emit to this half's slot ----
    if (tid < OWp) {
        float mm = -CUDART_INF_F;
        #pragma unroll
        for (int p2 = 0; p2 < 2; p2++)
            #pragma unroll
            for (int bo = 0; bo < 3; bo++)
                mm = fmaxf(mm, PMM[p2 * 30 + bo * 10 + tid]);
        g_half[H][(((long)n * ODp + d) * OHp + h) * OWp + tid] = mm;
    }
}

// ---------------------------------------------------------------------------
// Kernel 3: combine the two od-halves and add bias_sum.
// ---------------------------------------------------------------------------
__global__ void combine_kernel(float* __restrict__ out) {
    int i = blockIdx.x * blockDim.x + threadIdx.x;
    if (i < NOUT)
        out[i] = fmaxf(g_half[0][i], g_half[1][i]) + g_wsum_pad[6400];
}

// ---------------------------------------------------------------------------
extern "C" void kernel_launch(void* const* d_in, const int* in_sizes, int n_in,
                              void* d_out, int out_size) {
    (void)in_sizes; (void)n_in; (void)out_size;
    const float* x      = (const float*)d_in[0];
    const float* weight = (const float*)d_in[1];
    const float* bias   = (const float*)d_in[2];
    float* out = (float*)d_out;

    prep_kernel<<<26, 256>>>(weight, bias);
    fused_kernel<<<dim3(OHp, ODp, NB * 2), 128, SMEM_BYTES>>>(x);
    combine_kernel<<<(NOUT + 255) / 256, 256>>>(out);
}

// round 13
// speedup vs baseline: 1.2343x; 1.2343x over previous
#include <cuda_runtime.h>
#include <math_constants.h>

// Problem constants (from reference setup_inputs)
static constexpr int NB  = 16;   // batch
static constexpr int CIN = 32;   // input channels
static constexpr int DIN = 16;
static constexpr int HIN = 32;
static constexpr int WIN = 32;
static constexpr int ODp = 5;    // pooled output dims
static constexpr int OHp = 10;
static constexpr int OWp = 10;
static constexpr int NOUT = NB * ODp * OHp * OWp;   // 8000

// 4 chunks of 8 channels staged; each of 4 warps computes 2 of the 8.
static constexpr int CHUNK = 8;
static constexpr int CPG   = 2;                        // channels per warp-group
static constexpr int LWP   = 33;                       // padded x row (conflict-free)
static constexpr int XS_ELEMS = CHUNK * 5 * 5 * LWP;   // 6600
static constexpr int PM_ELEMS = 4 * 30 * 36;           // [group][cell][pt]
static constexpr int PMM_ELEMS = 30;
static constexpr int SMEM_BYTES = (XS_ELEMS + PM_ELEMS + PMM_ELEMS) * 4; // 43,800 B

// wsum padded: [c][kd*5+kh][8] (5 kw + 3 ZERO pads -> {W4,0} 64-bit loads);
// [6400] = bias_sum
__device__ float g_wsum_pad[6404];
// Per-oh-parity pooled maxima (pre-bias), combined by pass 2 (pure max).
__device__ float g_half[2][NOUT];

typedef unsigned long long ull;

#define FMA2(d, a, b) \
    asm("fma.rn.f32x2 %0, %1, %2, %0;" : "+l"(d) : "l"(a), "l"(b))

__device__ __forceinline__ ull bcast2(float x) {
    ull r;
    asm("mov.b64 %0, {%1, %1};" : "=l"(r) : "f"(x));
    return r;
}
__device__ __forceinline__ float2 unpack2(ull v) {
    float lo, hi;
    asm("mov.b64 {%0, %1}, %2;" : "=f"(lo), "=f"(hi) : "l"(v));
    return make_float2(lo, hi);
}

// ---------------------------------------------------------------------------
// Kernel 1 (coalesced): one block per channel c. Lanes map to contiguous k
// (coalesced 128B lines); two o-halves of 32 summed via smem.
// weight layout: (32,64,5,5,5) -> c*8000 + o*125 + k
// ---------------------------------------------------------------------------
__global__ void prep_kernel(const float* __restrict__ weight,
                            const float* __restrict__ bias) {
    __shared__ float sh[125];
    const int c = blockIdx.x;
    const int t = threadIdx.x;           // 256
    const int k    = (t < 250) ? (t % 125) : 0;
    const int half = (t < 250) ? (t / 125) : 0;

    float s = 0.f;
    if (t < 250) {
        const float* p = weight + c * 8000 + half * (32 * 125) + k;
        #pragma unroll
        for (int o = 0; o < 32; o++) s += p[o * 125];
    }
    if (t >= 125 && t < 250) sh[k] = s;
    __syncthreads();

    if (t < 125) {
        float tot = s + sh[t];
        g_wsum_pad[c * 200 + (t / 5) * 8 + (t % 5)] = tot;
    } else if (t >= 128 && t < 203) {     // zero the 25*3 pad slots
        int i = t - 128;
        int row = i / 3, col = 5 + i - row * 3;
        g_wsum_pad[c * 200 + row * 8 + col] = 0.f;
    } else if (c == 0 && t == 255) {
        float bs = 0.f;
        #pragma unroll
        for (int o = 0; o < 64; o++) bs += bias[o];
        g_wsum_pad[6400] = bs;
    }
}

// ---------------------------------------------------------------------------
// Per-chunk compute for oh-parity PB, channels [C0, C0+CPG).
// Thread owns all 6 od x 6 ow = 36 y partials as 18 f32x2 accumulators
// acc[od*3 + owpair].  Identity: od = 2*ld + kd - 4, valid in [0,5].
// Each X row is loaded once (5 LDS) and applied to all valid kd taps.
// ---------------------------------------------------------------------------
template <int PB>
__device__ __forceinline__ void compute_chunk(const float* __restrict__ XS,
                                              const float* __restrict__ gw,
                                              int C0, int b_off, int w,
                                              ull (&acc)[18]) {
    constexpr int NT = 3 - PB;   // # kh taps
    const int xcol = 3 * w;

    for (int c = C0; c < C0 + CPG; c++) {
        const float* XC = XS + c * (25 * LWP);
        const float* WC = gw + c * 200;
        #pragma unroll
        for (int t = 0; t < NT; t++) {
            const int lh = b_off + 2 - t;
            const int kh = PB + 2 * t;
            // Hoist all 5 kd weight rows for this kh (uniform 64-bit LDG).
            ull W01[5], W23[5], W40[5];
            #pragma unroll
            for (int kd = 0; kd < 5; kd++) {
                const ull* wr = reinterpret_cast<const ull*>(
                    WC + (kd * 5 + kh) * 8);
                W01[kd] = __ldg(wr);
                W23[kd] = __ldg(wr + 1);
                W40[kd] = __ldg(wr + 2);   // {W4, 0} thanks to zero padding
            }
            #pragma unroll
            for (int ld = 0; ld < 5; ld++) {
                const float* Xr = XC + (ld * 5 + lh) * LWP + xcol;
                const ull XX0 = bcast2(Xr[0]);
                const ull XX1 = bcast2(Xr[1]);
                const ull XX2 = bcast2(Xr[2]);
                const ull XX3 = bcast2(Xr[3]);
                const ull XX4 = bcast2(Xr[4]);
                #pragma unroll
                for (int kd = 0; kd < 5; kd++) {
                    const int od = 2 * ld + kd - 4;
                    if (od < 0 || od > 5) continue;   // folds at compile time
                    ull* P = acc + od * 3;
                    FMA2(P[0], XX2, W01[kd]);
                    FMA2(P[0], XX1, W23[kd]);
                    FMA2(P[0], XX0, W40[kd]);
                    FMA2(P[1], XX3, W01[kd]);
                    FMA2(P[1], XX2, W23[kd]);
                    FMA2(P[1], XX1, W40[kd]);
                    FMA2(P[2], XX4, W01[kd]);
                    FMA2(P[2], XX3, W23[kd]);
                    FMA2(P[2], XX2, W40[kd]);
                }
            }
        }
    }
}

// ---------------------------------------------------------------------------
// Kernel 2: fused transposed-conv (channel-summed) + oh-parity half of the
// 6x6x6 pool.  Block = (n, d, h, pb); 128 threads = 4 EQUAL warps, each
// owning 2 channels of every staged 8-channel chunk (no barrier skew).
// Lanes 0..29 own (b_off, w); each thread computes 36 y-partials.
// pb0 blocks (grid z < 16) are heavier and launch first.
// ---------------------------------------------------------------------------
__global__ __launch_bounds__(128, 5)
void fused_kernel(const float* __restrict__ x) {
    extern __shared__ float smem[];
    float* XS  = smem;                          // [8][5][5][LWP]
    float* PM  = smem + XS_ELEMS;               // [4 group][30][36]
    float* PMM = PM + PM_ELEMS;                 // [30]

    const int h  = blockIdx.x;
    const int d  = blockIdx.y;
    const int pb = blockIdx.z >> 4;             // oh parity (z = pb*16 + n)
    const int n  = blockIdx.z & 15;
    const int tid   = threadIdx.x;
    const int wid   = tid >> 5;
    const int lane  = tid & 31;
    const int group = wid;                 // channel pair within each chunk
    const int C0    = group * CPG;
    const int b_off = lane / 10;           // 0..2 (lanes 30,31: garbage, unstored)
    const int w     = lane - b_off * 10;

    const int id0 = 3 * d - 1;
    const int ih0 = 3 * h - 1;
    const float* xn = x + (long)n * (CIN * DIN * HIN * WIN);

    // --- precompute staging row tables: rows r = wid + 4*rr, rr < 7 ---
    bool rok[7], vld[7];
    int  goff[7], doff[7];
    #pragma unroll
    for (int rr = 0; rr < 7; rr++) {
        int r  = wid + 4 * rr;
        rok[rr] = (r < 25);
        int rc = r < 25 ? r : 24;
        int ld = rc / 5;
        int lh = rc - ld * 5;
        int id = id0 + ld;
        int ih = ih0 + lh;
        vld[rr]  = (id >= 0) && (ih >= 0);   // upper bounds always in range
        goff[rr] = id * (HIN * WIN) + ih * WIN + lane;
        doff[rr] = rc * LWP + 1 + lane;      // lw = iw + 1
    }

    ull acc[18];
    #pragma unroll
    for (int i = 0; i < 18; i++) acc[i] = 0ull;

    for (int chunk = 0; chunk < 4; chunk++) {
        if (chunk) __syncthreads();          // protect XS before re-staging
        // ---- stage x chunk (8 channels): lanes map 1:1 to iw, coalesced ----
        const float* xc = xn + chunk * (CHUNK * DIN * HIN * WIN);
        for (int c = 0; c < CHUNK; c++) {
            const int bg = c * (DIN * HIN * WIN);
            const int bd = c * (25 * LWP);
            #pragma unroll
            for (int rr = 0; rr < 7; rr++) {
                if (rok[rr]) {
                    float v = vld[rr] ? __ldg(xc + bg + goff[rr]) : 0.f;
                    XS[bd + doff[rr]] = v;
                    if (lane == 0) XS[bd + doff[rr] - 1] = 0.f;  // lw=0 pad col
                }
            }
        }
        __syncthreads();

        const float* gw = g_wsum_pad + chunk * (CHUNK * 200);
        if (pb == 0) compute_chunk<0>(XS, gw, C0, b_off, w, acc);
        else         compute_chunk<1>(XS, gw, C0, b_off, w, acc);
    }
    __syncthreads();

    // ---- store this group's 36 channel-partials for the cell ----
    if (lane < 30) {
        float* P = PM + (group * 30 + lane) * 36;
        #pragma unroll
        for (int i = 0; i < 18; i++) {
            float2 v = unpack2(acc[i]);
            P[2 * i]     = v.x;
            P[2 * i + 1] = v.y;
        }
    }
    __syncthreads();

    // ---- per cell: sum the 4 channel-groups, max over 36 pts ----
    if (tid < 30) {
        const float* A = PM + tid * 36;
        float m = -CUDART_INF_F;
        #pragma unroll
        for (int i = 0; i < 36; i++) {
            float y = A[i] + A[30 * 36 + i] + A[60 * 36 + i] + A[90 * 36 + i];
            m = fmaxf(m, y);
        }
        PMM[tid] = m;
    }
    __syncthreads();

    // ---- final: max over b_off, emit to this parity's slot ----
    if (tid < OWp) {
        float mm = fmaxf(fmaxf(PMM[tid], PMM[10 + tid]), PMM[20 + tid]);
        g_half[pb][(((long)n * ODp + d) * OHp + h) * OWp + tid] = mm;
    }
}

// ---------------------------------------------------------------------------
// Kernel 3: combine the two oh-parity halves (pure max) and add bias_sum.
// ---------------------------------------------------------------------------
__global__ void combine_kernel(float* __restrict__ out) {
    int i = blockIdx.x * blockDim.x + threadIdx.x;
    if (i < NOUT)
        out[i] = fmaxf(g_half[0][i], g_half[1][i]) + g_wsum_pad[6400];
}

// ---------------------------------------------------------------------------
extern "C" void kernel_launch(void* const* d_in, const int* in_sizes, int n_in,
                              void* d_out, int out_size) {
    (void)in_sizes; (void)n_in; (void)out_size;
    const float* x      = (const float*)d_in[0];
    const float* weight = (const float*)d_in[1];
    const float* bias   = (const float*)d_in[2];
    float* out = (float*)d_out;

    prep_kernel<<<32, 256>>>(weight, bias);
    fused_kernel<<<dim3(OHp, ODp, NB * 2), 128, SMEM_BYTES>>>(x);
    combine_kernel<<<(NOUT + 255) / 256, 256>>>(out);
}

// round 14
// speedup vs baseline: 1.4288x; 1.1576x over previous
#include <cuda_runtime.h>
#include <math_constants.h>
#include <cstdint>

// Problem constants (from reference setup_inputs)
static constexpr int NB  = 16;   // batch
static constexpr int CIN = 32;   // input channels
static constexpr int DIN = 16;
static constexpr int HIN = 32;
static constexpr int WIN = 32;
static constexpr int ODp = 5;    // pooled output dims
static constexpr int OHp = 10;
static constexpr int OWp = 10;

// 4 chunks of 8 channels staged; each warp computes 4 (its channel half).
static constexpr int CHUNK = 8;
static constexpr int CPG   = 4;                        // channels per group
static constexpr int LWP   = 33;                       // padded x row (conflict-free)
static constexpr int XS_ELEMS  = CHUNK * 5 * 5 * LWP;  // 6600
static constexpr int PM2_ELEMS = 2 * 2 * 30 * 36;      // [pb][group][cell][pt]
static constexpr int PMM_ELEMS = 60;
static constexpr int SMEM_BYTES = (XS_ELEMS + PM2_ELEMS + PMM_ELEMS) * 4; // 43,920 B

// wsum padded: [c][kd*5+kh][8] (5 kw + 3 ZERO pads -> {W4,0} 64-bit loads);
// [6400] = bias_sum
__device__ float g_wsum_pad[6404];

typedef unsigned long long ull;

#define FMA2(d, a, b) \
    asm("fma.rn.f32x2 %0, %1, %2, %0;" : "+l"(d) : "l"(a), "l"(b))

__device__ __forceinline__ ull bcast2(float x) {
    ull r;
    asm("mov.b64 %0, {%1, %1};" : "=l"(r) : "f"(x));
    return r;
}
__device__ __forceinline__ float2 unpack2(ull v) {
    float lo, hi;
    asm("mov.b64 {%0, %1}, %2;" : "=f"(lo), "=f"(hi) : "l"(v));
    return make_float2(lo, hi);
}
__device__ __forceinline__ uint32_t smem_u32(const void* p) {
    uint32_t a;
    asm("{ .reg .u64 t; cvta.to.shared.u64 t, %1; cvt.u32.u64 %0, t; }"
        : "=r"(a) : "l"(p));
    return a;
}
// 4-byte async copy with zero-fill: copies min(ssz,4) bytes, zero-fills rest.
__device__ __forceinline__ void cp4_zfill(uint32_t saddr, const void* gptr, int ssz) {
    asm volatile("cp.async.ca.shared.global [%0], [%1], 4, %2;"
                 :: "r"(saddr), "l"(gptr), "r"(ssz) : "memory");
}
__device__ __forceinline__ void cp_async_commit_wait_all() {
    asm volatile("cp.async.commit_group;" ::: "memory");
    asm volatile("cp.async.wait_group 0;" ::: "memory");
}

// ---------------------------------------------------------------------------
// Kernel 1 (coalesced): one block per channel c. Lanes map to contiguous k
// (coalesced 128B lines); two o-halves of 32 summed via smem.
// weight layout: (32,64,5,5,5) -> c*8000 + o*125 + k
// ---------------------------------------------------------------------------
__global__ void prep_kernel(const float* __restrict__ weight,
                            const float* __restrict__ bias) {
    __shared__ float sh[125];
    const int c = blockIdx.x;
    const int t = threadIdx.x;           // 256
    const int k    = (t < 250) ? (t % 125) : 0;
    const int half = (t < 250) ? (t / 125) : 0;

    float s = 0.f;
    if (t < 250) {
        const float* p = weight + c * 8000 + half * (32 * 125) + k;
        #pragma unroll
        for (int o = 0; o < 32; o++) s += p[o * 125];
    }
    if (t >= 125 && t < 250) sh[k] = s;
    __syncthreads();

    if (t < 125) {
        float tot = s + sh[t];
        g_wsum_pad[c * 200 + (t / 5) * 8 + (t % 5)] = tot;
    } else if (t >= 128 && t < 203) {     // zero the 25*3 pad slots
        int i = t - 128;
        int row = i / 3, col = 5 + i - row * 3;
        g_wsum_pad[c * 200 + row * 8 + col] = 0.f;
    } else if (c == 0 && t == 255) {
        float bs = 0.f;
        #pragma unroll
        for (int o = 0; o < 64; o++) bs += bias[o];
        g_wsum_pad[6400] = bs;
    }
}

// ---------------------------------------------------------------------------
// Per-chunk compute for oh-parity PB, channels [C0, C0+CPG).
// Thread owns all 6 od x 6 ow = 36 y partials as 18 f32x2 accumulators
// acc[od*3 + owpair].  Identity: od = 2*ld + kd - 4, valid in [0,5].
// Each X row is loaded once (5 LDS) and applied to all valid kd taps.
// Weights read as warp-uniform 64-bit __ldg broadcasts from g_wsum_pad.
// ---------------------------------------------------------------------------
template <int PB>
__device__ __forceinline__ void compute_chunk(const float* __restrict__ XS,
                                              const float* __restrict__ gw,
                                              int C0, int b_off, int w,
                                              ull (&acc)[18]) {
    constexpr int NT = 3 - PB;   // # kh taps
    const int xcol = 3 * w;

    for (int c = C0; c < C0 + CPG; c++) {
        const float* XC = XS + c * (25 * LWP);
        const float* WC = gw + c * 200;
        #pragma unroll
        for (int t = 0; t < NT; t++) {
            const int lh = b_off + 2 - t;
            const int kh = PB + 2 * t;
            // Hoist all 5 kd weight rows for this kh (uniform 64-bit LDG).
            ull W01[5], W23[5], W40[5];
            #pragma unroll
            for (int kd = 0; kd < 5; kd++) {
                const ull* wr = reinterpret_cast<const ull*>(
                    WC + (kd * 5 + kh) * 8);
                W01[kd] = __ldg(wr);
                W23[kd] = __ldg(wr + 1);
                W40[kd] = __ldg(wr + 2);   // {W4, 0} thanks to zero padding
            }
            #pragma unroll
            for (int ld = 0; ld < 5; ld++) {
                const float* Xr = XC + (ld * 5 + lh) * LWP + xcol;
                const ull XX0 = bcast2(Xr[0]);
                const ull XX1 = bcast2(Xr[1]);
                const ull XX2 = bcast2(Xr[2]);
                const ull XX3 = bcast2(Xr[3]);
                const ull XX4 = bcast2(Xr[4]);
                #pragma unroll
                for (int kd = 0; kd < 5; kd++) {
                    const int od = 2 * ld + kd - 4;
                    if (od < 0 || od > 5) continue;   // folds at compile time
                    ull* P = acc + od * 3;
                    FMA2(P[0], XX2, W01[kd]);
                    FMA2(P[0], XX1, W23[kd]);
                    FMA2(P[0], XX0, W40[kd]);
                    FMA2(P[1], XX3, W01[kd]);
                    FMA2(P[1], XX2, W23[kd]);
                    FMA2(P[1], XX1, W40[kd]);
                    FMA2(P[2], XX4, W01[kd]);
                    FMA2(P[2], XX3, W23[kd]);
                    FMA2(P[2], XX2, W40[kd]);
                }
            }
        }
    }
}

// ---------------------------------------------------------------------------
// Kernel 2: fused transposed-conv (channel-summed) + 6x6x6/6 max pool.
// Block = (n, d, h); 128 threads = 4 warps = (pb, channel-half); pb mapping
// swapped by block parity so SMSPs average the pb0/pb1 load across CTAs.
// Lanes 0..29 own (b_off, w); each thread computes 36 y-partials.
// Staging uses cp.async with zero-fill (no LDG->reg->STS round trip).
// ---------------------------------------------------------------------------
__global__ __launch_bounds__(128, 5)
void fused_kernel(const float* __restrict__ x, float* __restrict__ out) {
    extern __shared__ float smem[];
    float* XS  = smem;                          // [8][5][5][LWP]
    float* PM2 = smem + XS_ELEMS;               // [2 pb][2 group][30][36]
    float* PMM = PM2 + PM2_ELEMS;               // [2 pb][30]

    const int h = blockIdx.x;
    const int d = blockIdx.y;
    const int n = blockIdx.z;
    const int tid   = threadIdx.x;
    const int wid   = tid >> 5;
    const int lane  = tid & 31;
    const int par   = (blockIdx.x + blockIdx.y + blockIdx.z) & 1;
    const int pb    = (wid >> 1) ^ par;    // oh parity (block-parity swapped)
    const int group = wid & 1;             // channel half
    const int C0    = group * CPG;
    const int b_off = lane / 10;           // 0..2 (lanes 30,31: garbage, unstored)
    const int w     = lane - b_off * 10;

    const int id0 = 3 * d - 1;
    const int ih0 = 3 * h - 1;
    const float* xn = x + (long)n * (CIN * DIN * HIN * WIN);
    const uint32_t xs_base = smem_u32(XS);

    // --- precompute staging row tables: rows r = wid + 4*rr, rr < 7 ---
    bool rok[7];
    int  goff[7], doff[7], ssz[7];
    #pragma unroll
    for (int rr = 0; rr < 7; rr++) {
        int r  = wid + 4 * rr;
        rok[rr] = (r < 25);
        int rc = r < 25 ? r : 24;
        int ld = rc / 5;
        int lh = rc - ld * 5;
        int id = id0 + ld;
        int ih = ih0 + lh;
        bool v   = (id >= 0) && (ih >= 0);   // upper bounds always in range
        ssz[rr]  = v ? 4 : 0;                // cp.async zero-fill for halo
        goff[rr] = v ? (id * (HIN * WIN) + ih * WIN + lane) : 0;
        doff[rr] = rc * LWP + 1 + lane;      // lw = iw + 1
    }

    // --- zero the lw=0 pad column once; staging never overwrites it ---
    for (int r = tid; r < CHUNK * 25; r += 128) XS[r * LWP] = 0.f;

    ull acc[18];
    #pragma unroll
    for (int i = 0; i < 18; i++) acc[i] = 0ull;

    for (int chunk = 0; chunk < 4; chunk++) {
        if (chunk) __syncthreads();          // protect XS before re-staging
        // ---- stage x chunk (8 ch) via cp.async: lanes 1:1 to iw, coalesced ----
        const float* xc = xn + chunk * (CHUNK * DIN * HIN * WIN);
        for (int c = 0; c < CHUNK; c++) {
            const float* bgp = xc + c * (DIN * HIN * WIN);
            const uint32_t bd = xs_base + c * (25 * LWP) * 4;
            #pragma unroll
            for (int rr = 0; rr < 7; rr++) {
                if (rok[rr])
                    cp4_zfill(bd + doff[rr] * 4, bgp + goff[rr], ssz[rr]);
            }
        }
        cp_async_commit_wait_all();
        __syncthreads();

        const float* gw = g_wsum_pad + chunk * (CHUNK * 200);
        if (pb == 0) compute_chunk<0>(XS, gw, C0, b_off, w, acc);
        else         compute_chunk<1>(XS, gw, C0, b_off, w, acc);
    }
    __syncthreads();

    // ---- store this (pb, group) 36 channel-partials for the cell ----
    if (lane < 30) {
        float* P = PM2 + ((pb * 2 + group) * 30 + lane) * 36;
        #pragma unroll
        for (int i = 0; i < 18; i++) {
            float2 v = unpack2(acc[i]);
            P[2 * i]     = v.x;
            P[2 * i + 1] = v.y;
        }
    }
    __syncthreads();

    // ---- per (pb, cell): sum the two channel-groups, max over 36 pts ----
    if (tid < 60) {
        const int p2   = tid / 30;
        const int cell = tid - p2 * 30;
        const float* A = PM2 + (p2 * 2 * 30 + cell) * 36;   // group 0
        const float* B = A + 30 * 36;                        // group 1
        float m = -CUDART_INF_F;
        #pragma unroll
        for (int i = 0; i < 36; i++) m = fmaxf(m, A[i] + B[i]);
        PMM[p2 * 30 + cell] = m;
    }
    __syncthreads();

    // ---- final: max over pb and b_off, add bias_sum, emit ----
    if (tid < OWp) {
        float mm = -CUDART_INF_F;
        #pragma unroll
        for (int p2 = 0; p2 < 2; p2++)
            #pragma unroll
            for (int bo = 0; bo < 3; bo++)
                mm = fmaxf(mm, PMM[p2 * 30 + bo * 10 + tid]);
        const float bs = g_wsum_pad[6400];
        out[(((long)n * ODp + d) * OHp + h) * OWp + tid] = mm + bs;
    }
}

// ---------------------------------------------------------------------------
extern "C" void kernel_launch(void* const* d_in, const int* in_sizes, int n_in,
                              void* d_out, int out_size) {
    (void)in_sizes; (void)n_in; (void)out_size;
    const float* x      = (const float*)d_in[0];
    const float* weight = (const float*)d_in[1];
    const float* bias   = (const float*)d_in[2];
    float* out = (float*)d_out;

    prep_kernel<<<32, 256>>>(weight, bias);
    fused_kernel<<<dim3(OHp, ODp, NB), 128, SMEM_BYTES>>>(x, out);
}